// round 1
// baseline (speedup 1.0000x reference)
#include <cuda_runtime.h>
#include <math.h>

#define BATCH 64
#define NG    32
#define CIN   128
#define COUT  128
#define LMAX  16
#define NR    (BATCH*LMAX*2)   // 2048 rows (b,m,ri) for stage C

// ---------------- scratch (device globals; no allocation allowed) ----------
__device__ float g_F[(size_t)BATCH*LMAX*2*NG*CIN];     // [b][m][ri][j][i]  33.5MB
__device__ float g_coef[(size_t)LMAX*NR*CIN];          // [l][r][i]         16.8MB
__device__ float g_chat[(size_t)LMAX*NR*COUT];         // [l][r][o]         16.8MB
__device__ float g_G[(size_t)BATCH*NG*LMAX*2*COUT];    // [b][j][m][ri][o]  33.5MB
__device__ float g_Qw[LMAX*LMAX*NG];                   // [l][m][j] * wj * s_l
__device__ float g_Qs[LMAX*LMAX*NG];                   // [l][m][j] * k_m
__device__ float g_cosT[LMAX*NG];                      // [m][p]
__device__ float g_sinT[LMAX*NG];

// ---------------- init: Legendre + trig tables (fp64, tiny) ----------------
__global__ void init_tables() {
    int j = threadIdx.x;                  // 0..31 (theta / phi index)
    double theta = M_PI * (j + 0.5) / NG;
    double cx = cos(theta), sx = sin(theta);
    double wj = sx * (M_PI / NG) * (2.0 * M_PI / NG);

    for (int l = 0; l < LMAX; l++)
        for (int m = 0; m < LMAX; m++) {
            g_Qw[(l*LMAX+m)*NG + j] = 0.f;
            g_Qs[(l*LMAX+m)*NG + j] = 0.f;
        }

    double Pmm = 1.0;                      // P[m][m]
    for (int m = 0; m < LMAX; m++) {
        double invf = 1.0;                 // (l-m)!/(l+m)! at l=m : 1/(2m)!
        for (int t = 1; t <= 2*m; t++) invf /= (double)t;
        double rat = invf;
        double pl_2 = 0.0, pl_1 = 0.0, pl = 0.0;
        for (int l = m; l < LMAX; l++) {
            if (l == m)        pl = Pmm;
            else if (l == m+1) pl = (2.0*m + 1.0) * cx * Pmm;
            else               pl = ((2.0*l - 1.0)*cx*pl_1 - (l + m - 1.0)*pl_2) / (double)(l - m);
            double Nlm = sqrt((2.0*l + 1.0) / (4.0*M_PI) * rat);
            double q   = Nlm * pl;
            double sl  = 2.0*M_PI * sqrt(4.0*M_PI / (2.0*l + 1.0));
            double km  = (m == 0) ? 1.0 : 2.0;
            g_Qw[(l*LMAX+m)*NG + j] = (float)(q * wj * sl);
            g_Qs[(l*LMAX+m)*NG + j] = (float)(q * km);
            pl_2 = pl_1; pl_1 = pl;
            rat *= (double)(l + 1 - m) / (double)(l + 1 + m);
        }
        Pmm = -(2.0*m + 1.0) * sx * Pmm;   // P[m+1][m+1]
    }

    for (int m = 0; m < LMAX; m++) {
        double a = 2.0 * M_PI * (double)m * (double)j / (double)NG;
        g_cosT[m*NG + j] = (float)cos(a);
        g_sinT[m*NG + j] = (float)sin(a);
    }
}

// ---------------- A: real DFT over phi, keep m=0..15 -----------------------
__global__ void kA(const float* __restrict__ in) {
    int bj = blockIdx.x;                  // b*32 + j (theta)
    int b = bj >> 5, j = bj & 31;
    int i = threadIdx.x;                  // channel
    __shared__ float sc[LMAX*NG], ss[LMAX*NG];
    for (int t = i; t < LMAX*NG; t += 128) { sc[t] = g_cosT[t]; ss[t] = g_sinT[t]; }
    __syncthreads();

    float xp[NG];
    const float* src = in + (size_t)bj * NG * CIN + i;
#pragma unroll
    for (int p = 0; p < NG; p++) xp[p] = src[p*CIN];

#pragma unroll
    for (int m = 0; m < LMAX; m++) {
        float fr = 0.f, fi = 0.f;
#pragma unroll
        for (int p = 0; p < NG; p++) {
            fr += xp[p] * sc[m*NG + p];
            fi -= xp[p] * ss[m*NG + p];
        }
        g_F[((((size_t)b*LMAX + m)*2 + 0)*NG + j)*CIN + i] = fr;
        g_F[((((size_t)b*LMAX + m)*2 + 1)*NG + j)*CIN + i] = fi;
    }
}

// ---------------- B: Legendre analysis (quadrature over theta) -------------
__global__ void kB() {
    int r = blockIdx.x;                   // (b*16+m)*2+ri
    int m = (r >> 1) & 15;
    int i = threadIdx.x;
    __shared__ float sq[LMAX*NG];         // Qw[l][m][*] for this m
    for (int t = i; t < LMAX*NG; t += 128) {
        int l = t >> 5, j = t & 31;
        sq[t] = g_Qw[(l*LMAX + m)*NG + j];
    }
    __syncthreads();

    float f[NG];
    const float* src = g_F + (size_t)r * NG * CIN + i;
#pragma unroll
    for (int j = 0; j < NG; j++) f[j] = src[j*CIN];

#pragma unroll
    for (int l = 0; l < LMAX; l++) {
        float c = 0.f;
#pragma unroll
        for (int j = 0; j < NG; j++) c += sq[l*NG + j] * f[j];
        g_coef[((size_t)l*NR + r)*CIN + i] = c;
    }
}

// ---------------- C: per-degree channel mix, 16x GEMM 2048x128x128 ---------
__global__ void kC(const float* __restrict__ w) {
    int l = blockIdx.y, mt = blockIdx.x;  // 64-row M tile
    const float* A = g_coef + (size_t)l*NR*CIN + (size_t)mt*64*CIN;
    const float* B = w + l*COUT;          // w[i][l][o]
    float* C = g_chat + (size_t)l*NR*COUT + (size_t)mt*64*COUT;

    __shared__ float As[64][17];
    __shared__ float Bs[16][128];
    int tid = threadIdx.x;
    int ty = tid >> 5, tx = tid & 31;     // warp row-group / lane col-group
    float acc[8][4] = {};

    for (int k0 = 0; k0 < CIN; k0 += 16) {
        for (int t = tid; t < 64*16; t += 256) {
            int r = t >> 4, k = t & 15;
            As[r][k] = A[r*CIN + k0 + k];
        }
        for (int t = tid; t < 16*128; t += 256) {
            int k = t >> 7, o = t & 127;
            Bs[k][o] = B[(size_t)(k0 + k) * (LMAX*COUT) + o];
        }
        __syncthreads();
#pragma unroll
        for (int k = 0; k < 16; k++) {
            float a[8];
            float4 bb = *(const float4*)&Bs[k][tx*4];
#pragma unroll
            for (int rr = 0; rr < 8; rr++) a[rr] = As[ty*8 + rr][k];
#pragma unroll
            for (int rr = 0; rr < 8; rr++) {
                acc[rr][0] += a[rr] * bb.x;
                acc[rr][1] += a[rr] * bb.y;
                acc[rr][2] += a[rr] * bb.z;
                acc[rr][3] += a[rr] * bb.w;
            }
        }
        __syncthreads();
    }
#pragma unroll
    for (int rr = 0; rr < 8; rr++) {
        float4 v = make_float4(acc[rr][0], acc[rr][1], acc[rr][2], acc[rr][3]);
        *(float4*)&C[(ty*8 + rr)*COUT + tx*4] = v;
    }
}

// ---------------- D: Legendre synthesis ------------------------------------
__global__ void kD() {
    int r = blockIdx.x;                   // (b*16+m)*2+ri
    int ri = r & 1, m = (r >> 1) & 15, b = r >> 5;
    int o = threadIdx.x;
    __shared__ float sq[LMAX*NG];         // Qs[l][m][*] (includes k_m)
    for (int t = o; t < LMAX*NG; t += 128) {
        int l = t >> 5, j = t & 31;
        sq[t] = g_Qs[(l*LMAX + m)*NG + j];
    }
    __syncthreads();

    float ch[LMAX];
#pragma unroll
    for (int l = 0; l < LMAX; l++) ch[l] = g_chat[((size_t)l*NR + r)*COUT + o];

#pragma unroll
    for (int j = 0; j < NG; j++) {
        float g = 0.f;
#pragma unroll
        for (int l = 0; l < LMAX; l++) g += sq[l*NG + j] * ch[l];
        g_G[(((((size_t)b*NG + j)*LMAX + m)*2 + ri))*COUT + o] = g;
    }
}

// ---------------- E: inverse real DFT over phi + bias ----------------------
__global__ void kE(const float* __restrict__ bias, float* __restrict__ out) {
    int bj = blockIdx.x;
    int o = threadIdx.x;
    __shared__ float sc[LMAX*NG], ss[LMAX*NG];
    for (int t = o; t < LMAX*NG; t += 128) { sc[t] = g_cosT[t]; ss[t] = g_sinT[t]; }
    __syncthreads();

    float gr[LMAX], gi[LMAX];
    const float* src = g_G + (size_t)bj * LMAX * 2 * COUT + o;
#pragma unroll
    for (int m = 0; m < LMAX; m++) {
        gr[m] = src[(m*2 + 0)*COUT];
        gi[m] = src[(m*2 + 1)*COUT];
    }
    float bv = bias[o];
    float* dst = out + (size_t)bj * NG * COUT + o;
#pragma unroll
    for (int p = 0; p < NG; p++) {
        float s = bv;
#pragma unroll
        for (int m = 0; m < LMAX; m++)
            s += gr[m]*sc[m*NG + p] - gi[m]*ss[m*NG + p];
        dst[p*COUT] = s;
    }
}

extern "C" void kernel_launch(void* const* d_in, const int* in_sizes, int n_in,
                              void* d_out, int out_size) {
    const float* in   = (const float*)d_in[0];
    const float* w    = (const float*)d_in[1];
    const float* bias = (const float*)d_in[2];
    float* out = (float*)d_out;

    init_tables<<<1, 32>>>();
    kA<<<BATCH*NG, 128>>>(in);
    kB<<<NR, 128>>>();
    kC<<<dim3(NR/64, LMAX), 256>>>(w);
    kD<<<NR, 128>>>();
    kE<<<BATCH*NG, 128>>>(bias, out);
}

// round 2
// speedup vs baseline: 2.3240x; 2.3240x over previous
#include <cuda_runtime.h>
#include <math.h>

#define BATCH 64
#define NG    32
#define CIN   128
#define COUT  128
#define LMAX  16
#define NR    (BATCH*LMAX*2)   // 2048 rows (b,m,ri) for stage C

// ---------------- scratch (device globals; no allocation allowed) ----------
__device__ float g_F[(size_t)BATCH*LMAX*2*NG*CIN];     // [b][m][ri][j][i]  33.5MB
__device__ float g_coef[(size_t)LMAX*NR*CIN];          // [l][r][i]         16.8MB
__device__ float g_chat[(size_t)LMAX*NR*COUT];         // [l][r][o]         16.8MB
__device__ float g_G[(size_t)BATCH*NG*LMAX*2*COUT];    // [b][j][m][ri][o]  33.5MB
__device__ float g_Qw[LMAX*LMAX*NG];                   // [l][m][j] * wj * s_l
__device__ float g_Qs[LMAX*LMAX*NG];                   // [l][m][j] * k_m
__device__ float g_cosT[LMAX*NG];                      // [m][p]
__device__ float g_sinT[LMAX*NG];

// ---------------- init: Legendre + trig tables, 512-way parallel -----------
__global__ void init_tables() {
    int t = threadIdx.x;                  // 0..511
    int m = t >> 5, j = t & 31;           // one thread per (m, j)
    double theta = M_PI * (j + 0.5) / NG;
    double cx = cos(theta), sx = sin(theta);
    double wj = sx * (M_PI / NG) * (2.0 * M_PI / NG);

    // entries with l < m are zero
    for (int l = 0; l < m; l++) {
        g_Qw[(l*LMAX + m)*NG + j] = 0.f;
        g_Qs[(l*LMAX + m)*NG + j] = 0.f;
    }

    // P[m][m] and (l-m)!/(l+m)! starting ratio 1/(2m)!
    double Pmm = 1.0, invf = 1.0;
    for (int mm = 1; mm <= m; mm++) Pmm = -(2.0*mm - 1.0) * sx * Pmm;
    for (int tt = 1; tt <= 2*m; tt++) invf /= (double)tt;
    double rat = invf;
    double pl_2 = 0.0, pl_1 = 0.0, pl = 0.0;
    for (int l = m; l < LMAX; l++) {
        if (l == m)        pl = Pmm;
        else if (l == m+1) pl = (2.0*m + 1.0) * cx * Pmm;
        else               pl = ((2.0*l - 1.0)*cx*pl_1 - (l + m - 1.0)*pl_2) / (double)(l - m);
        double Nlm = sqrt((2.0*l + 1.0) / (4.0*M_PI) * rat);
        double q   = Nlm * pl;
        double sl  = 2.0*M_PI * sqrt(4.0*M_PI / (2.0*l + 1.0));
        double km  = (m == 0) ? 1.0 : 2.0;
        g_Qw[(l*LMAX + m)*NG + j] = (float)(q * wj * sl);
        g_Qs[(l*LMAX + m)*NG + j] = (float)(q * km);
        pl_2 = pl_1; pl_1 = pl;
        rat *= (double)(l + 1 - m) / (double)(l + 1 + m);
    }

    // trig table row m, column p=j
    double a = 2.0 * M_PI * (double)m * (double)j / (double)NG;
    g_cosT[m*NG + j] = (float)cos(a);
    g_sinT[m*NG + j] = (float)sin(a);
}

// ---------------- A: real DFT over phi, keep m=0..15 -----------------------
__global__ void kA(const float* __restrict__ in) {
    int bj = blockIdx.x;                  // b*32 + j (theta)
    int b = bj >> 5, j = bj & 31;
    int i = threadIdx.x;                  // channel
    __shared__ float sc[LMAX*NG], ss[LMAX*NG];
    for (int t = i; t < LMAX*NG; t += 128) { sc[t] = g_cosT[t]; ss[t] = g_sinT[t]; }
    __syncthreads();

    float xp[NG];
    const float* src = in + (size_t)bj * NG * CIN + i;
#pragma unroll
    for (int p = 0; p < NG; p++) xp[p] = src[p*CIN];

#pragma unroll
    for (int m = 0; m < LMAX; m++) {
        float fr = 0.f, fi = 0.f;
#pragma unroll
        for (int p = 0; p < NG; p++) {
            fr += xp[p] * sc[m*NG + p];
            fi -= xp[p] * ss[m*NG + p];
        }
        g_F[((((size_t)b*LMAX + m)*2 + 0)*NG + j)*CIN + i] = fr;
        g_F[((((size_t)b*LMAX + m)*2 + 1)*NG + j)*CIN + i] = fi;
    }
}

// ---------------- B: Legendre analysis (quadrature over theta) -------------
__global__ void kB() {
    int r = blockIdx.x;                   // (b*16+m)*2+ri
    int m = (r >> 1) & 15;
    int i = threadIdx.x;
    __shared__ float sq[LMAX*NG];         // Qw[l][m][*] for this m
    for (int t = i; t < LMAX*NG; t += 128) {
        int l = t >> 5, j = t & 31;
        sq[t] = g_Qw[(l*LMAX + m)*NG + j];
    }
    __syncthreads();

    float f[NG];
    const float* src = g_F + (size_t)r * NG * CIN + i;
#pragma unroll
    for (int j = 0; j < NG; j++) f[j] = src[j*CIN];

#pragma unroll
    for (int l = 0; l < LMAX; l++) {
        float c = 0.f;
#pragma unroll
        for (int j = 0; j < NG; j++) c += sq[l*NG + j] * f[j];
        g_coef[((size_t)l*NR + r)*CIN + i] = c;
    }
}

// ---------------- C: per-degree channel mix, 16x GEMM 2048x128x128 ---------
// 128x128 tile per block, 256 threads, 8x8 micro-tile
__global__ void kC(const float* __restrict__ w) {
    int l = blockIdx.y, mt = blockIdx.x;  // 16 x 16
    const float* A = g_coef + ((size_t)l*NR + (size_t)mt*128)*CIN;
    const float* B = w + l*COUT;          // w[i][l][o], k-stride = LMAX*COUT
    float* C = g_chat + ((size_t)l*NR + (size_t)mt*128)*COUT;

    __shared__ float As[8][132];          // [k][row], padded
    __shared__ float Bs[8][128];          // [k][col]
    int tid = threadIdx.x;
    int tx = tid & 15, ty = tid >> 4;     // 16x16 thread grid
    float acc[8][8] = {};

    for (int k0 = 0; k0 < CIN; k0 += 8) {
#pragma unroll
        for (int e = 0; e < 4; e++) {
            int lin = tid + e*256;
            int r = lin >> 3, k = lin & 7;
            As[k][r] = A[r*CIN + k0 + k];
            int kk = lin >> 7, o = lin & 127;
            Bs[kk][o] = B[(size_t)(k0 + kk) * (LMAX*COUT) + o];
        }
        __syncthreads();
#pragma unroll
        for (int k = 0; k < 8; k++) {
            float4 a0 = *(const float4*)&As[k][ty*8];
            float4 a1 = *(const float4*)&As[k][ty*8 + 4];
            float4 b0 = *(const float4*)&Bs[k][tx*8];
            float4 b1 = *(const float4*)&Bs[k][tx*8 + 4];
            float av[8] = {a0.x,a0.y,a0.z,a0.w,a1.x,a1.y,a1.z,a1.w};
            float bv[8] = {b0.x,b0.y,b0.z,b0.w,b1.x,b1.y,b1.z,b1.w};
#pragma unroll
            for (int i2 = 0; i2 < 8; i2++)
#pragma unroll
                for (int j2 = 0; j2 < 8; j2++)
                    acc[i2][j2] += av[i2] * bv[j2];
        }
        __syncthreads();
    }
#pragma unroll
    for (int i2 = 0; i2 < 8; i2++) {
        *(float4*)&C[(ty*8 + i2)*COUT + tx*8]     =
            make_float4(acc[i2][0], acc[i2][1], acc[i2][2], acc[i2][3]);
        *(float4*)&C[(ty*8 + i2)*COUT + tx*8 + 4] =
            make_float4(acc[i2][4], acc[i2][5], acc[i2][6], acc[i2][7]);
    }
}

// ---------------- D: Legendre synthesis ------------------------------------
__global__ void kD() {
    int r = blockIdx.x;                   // (b*16+m)*2+ri
    int ri = r & 1, m = (r >> 1) & 15, b = r >> 5;
    int o = threadIdx.x;
    __shared__ float sq[LMAX*NG];         // Qs[l][m][*] (includes k_m)
    for (int t = o; t < LMAX*NG; t += 128) {
        int l = t >> 5, j = t & 31;
        sq[t] = g_Qs[(l*LMAX + m)*NG + j];
    }
    __syncthreads();

    float ch[LMAX];
#pragma unroll
    for (int l = 0; l < LMAX; l++) ch[l] = g_chat[((size_t)l*NR + r)*COUT + o];

#pragma unroll
    for (int j = 0; j < NG; j++) {
        float g = 0.f;
#pragma unroll
        for (int l = 0; l < LMAX; l++) g += sq[l*NG + j] * ch[l];
        g_G[(((((size_t)b*NG + j)*LMAX + m)*2 + ri))*COUT + o] = g;
    }
}

// ---------------- E: inverse real DFT over phi + bias ----------------------
__global__ void kE(const float* __restrict__ bias, float* __restrict__ out) {
    int bj = blockIdx.x;
    int o = threadIdx.x;
    __shared__ float sc[LMAX*NG], ss[LMAX*NG];
    for (int t = o; t < LMAX*NG; t += 128) { sc[t] = g_cosT[t]; ss[t] = g_sinT[t]; }
    __syncthreads();

    float gr[LMAX], gi[LMAX];
    const float* src = g_G + (size_t)bj * LMAX * 2 * COUT + o;
#pragma unroll
    for (int m = 0; m < LMAX; m++) {
        gr[m] = src[(m*2 + 0)*COUT];
        gi[m] = src[(m*2 + 1)*COUT];
    }
    float bv = bias[o];
    float* dst = out + (size_t)bj * NG * COUT + o;
#pragma unroll
    for (int p = 0; p < NG; p++) {
        float s = bv;
#pragma unroll
        for (int m = 0; m < LMAX; m++)
            s += gr[m]*sc[m*NG + p] - gi[m]*ss[m*NG + p];
        dst[p*COUT] = s;
    }
}

extern "C" void kernel_launch(void* const* d_in, const int* in_sizes, int n_in,
                              void* d_out, int out_size) {
    const float* in   = (const float*)d_in[0];
    const float* w    = (const float*)d_in[1];
    const float* bias = (const float*)d_in[2];
    float* out = (float*)d_out;

    init_tables<<<1, 512>>>();
    kA<<<BATCH*NG, 128>>>(in);
    kB<<<NR, 128>>>();
    kC<<<dim3(16, LMAX), 256>>>(w);
    kD<<<NR, 128>>>();
    kE<<<BATCH*NG, 128>>>(bias, out);
}

// round 3
// speedup vs baseline: 4.5256x; 1.9474x over previous
#include <cuda_runtime.h>
#include <math.h>

#define BATCH 64
#define NG    32
#define CIN   128
#define COUT  128
#define LMAX  16
#define NR    (BATCH*LMAX*2)   // 2048 rows (b,m,ri) for stage C

// ---------------- scratch (device globals; no allocation allowed) ----------
__device__ float g_F[(size_t)BATCH*LMAX*2*NG*CIN];     // [b][m][ri][j][i]  33.5MB
__device__ float g_coef[(size_t)LMAX*NR*CIN];          // [l][r][i]         16.8MB
__device__ float g_chat[(size_t)LMAX*NR*COUT];         // [l][r][o]         16.8MB
__device__ float g_G[(size_t)BATCH*NG*LMAX*2*COUT];    // [b][j][m][ri][o]  33.5MB
__device__ float g_Qw[LMAX*LMAX*NG];                   // [l][m][j] * wj * s_l
__device__ float g_Qs[LMAX*LMAX*NG];                   // [l][m][j] * k_m
__device__ float g_cosT[LMAX*NG];                      // [m][p]
__device__ float g_sinT[LMAX*NG];

// ---------------- init: Legendre + trig tables, fp32, 512-way parallel -----
__global__ void init_tables() {
    int t = threadIdx.x;                  // 0..511
    int m = t >> 5, j = t & 31;           // one thread per (m, j)
    float sx, cx;
    sincospif((j + 0.5f) / NG, &sx, &cx); // theta = pi*(j+0.5)/32
    float wj = sx * ((float)M_PI / NG) * (2.0f * (float)M_PI / NG);

    // entries with l < m are zero
    for (int l = 0; l < m; l++) {
        g_Qw[(l*LMAX + m)*NG + j] = 0.f;
        g_Qs[(l*LMAX + m)*NG + j] = 0.f;
    }

    // P[m][m] and (l-m)!/(l+m)! starting ratio 1/(2m)!
    float Pmm = 1.0f, invf = 1.0f;
    for (int mm = 1; mm <= m; mm++) Pmm = -(2.0f*mm - 1.0f) * sx * Pmm;
    for (int tt = 1; tt <= 2*m; tt++) invf /= (float)tt;
    float rat = invf;
    float pl_2 = 0.0f, pl_1 = 0.0f, pl = 0.0f;
    const float inv4pi = 1.0f / (4.0f * (float)M_PI);
    for (int l = m; l < LMAX; l++) {
        if (l == m)        pl = Pmm;
        else if (l == m+1) pl = (2.0f*m + 1.0f) * cx * Pmm;
        else               pl = ((2.0f*l - 1.0f)*cx*pl_1 - (l + m - 1.0f)*pl_2) / (float)(l - m);
        float Nlm = sqrtf((2.0f*l + 1.0f) * inv4pi * rat);
        float q   = Nlm * pl;
        float sl  = 2.0f*(float)M_PI * sqrtf(4.0f*(float)M_PI / (2.0f*l + 1.0f));
        float km  = (m == 0) ? 1.0f : 2.0f;
        g_Qw[(l*LMAX + m)*NG + j] = q * wj * sl;
        g_Qs[(l*LMAX + m)*NG + j] = q * km;
        pl_2 = pl_1; pl_1 = pl;
        rat *= (float)(l + 1 - m) / (float)(l + 1 + m);
    }

    // trig table row m, column p=j (sincospi is exact at these rationals)
    float sa, ca;
    sincospif(2.0f * (float)m * (float)j / (float)NG, &sa, &ca);
    g_cosT[m*NG + j] = ca;
    g_sinT[m*NG + j] = sa;
}

// ---------------- A: real DFT over phi, keep m=0..15 -----------------------
__global__ void __launch_bounds__(128) kA(const float* __restrict__ in) {
    int bj = blockIdx.x;                  // b*32 + j (theta)
    int b = bj >> 5, j = bj & 31;
    int i = threadIdx.x;                  // channel
    __shared__ float sc[LMAX*NG], ss[LMAX*NG];
    for (int t = i; t < LMAX*NG; t += 128) { sc[t] = g_cosT[t]; ss[t] = g_sinT[t]; }
    __syncthreads();

    float xp[NG];
    const float* src = in + (size_t)bj * NG * CIN + i;
#pragma unroll
    for (int p = 0; p < NG; p++) xp[p] = src[p*CIN];

#pragma unroll
    for (int m = 0; m < LMAX; m++) {
        float fr = 0.f, fi = 0.f;
#pragma unroll
        for (int p = 0; p < NG; p++) {
            fr += xp[p] * sc[m*NG + p];
            fi -= xp[p] * ss[m*NG + p];
        }
        g_F[((((size_t)b*LMAX + m)*2 + 0)*NG + j)*CIN + i] = fr;
        g_F[((((size_t)b*LMAX + m)*2 + 1)*NG + j)*CIN + i] = fi;
    }
}

// ---------------- B: Legendre analysis (quadrature over theta) -------------
__global__ void __launch_bounds__(128) kB() {
    int r = blockIdx.x;                   // (b*16+m)*2+ri
    int m = (r >> 1) & 15;
    int i = threadIdx.x;
    __shared__ float sq[LMAX*NG];         // Qw[l][m][*] for this m
    for (int t = i; t < LMAX*NG; t += 128) {
        int l = t >> 5, j = t & 31;
        sq[t] = g_Qw[(l*LMAX + m)*NG + j];
    }
    __syncthreads();

    float f[NG];
    const float* src = g_F + (size_t)r * NG * CIN + i;
#pragma unroll
    for (int j = 0; j < NG; j++) f[j] = src[j*CIN];

#pragma unroll
    for (int l = 0; l < LMAX; l++) {
        float c = 0.f;
#pragma unroll
        for (int j = 0; j < NG; j++) c += sq[l*NG + j] * f[j];
        g_coef[((size_t)l*NR + r)*CIN + i] = c;
    }
}

// ---------------- C: per-degree channel mix, 16x GEMM 2048x128x128 ---------
// 128x128 tile per block, 256 threads, 8x8 micro-tile, K-chunk 16
__global__ void __launch_bounds__(256, 2) kC(const float* __restrict__ w) {
    int l = blockIdx.y, mt = blockIdx.x;  // 16 x 16
    const float* A = g_coef + ((size_t)l*NR + (size_t)mt*128)*CIN;
    const float* B = w + l*COUT;          // w[i][l][o], k-stride = LMAX*COUT
    float* C = g_chat + ((size_t)l*NR + (size_t)mt*128)*COUT;

    __shared__ float As[16][132];         // [k][row], padded
    __shared__ float Bs[16][128];         // [k][col]
    int tid = threadIdx.x;
    int tx = tid & 15, ty = tid >> 4;     // 16x16 thread grid
    float acc[8][8] = {};

    for (int k0 = 0; k0 < CIN; k0 += 16) {
#pragma unroll
        for (int e = 0; e < 8; e++) {
            int lin = tid + e*256;
            int r = lin >> 4, k = lin & 15;
            As[k][r] = A[r*CIN + k0 + k];
            int kk = lin >> 7, o = lin & 127;
            Bs[kk][o] = B[(size_t)(k0 + kk) * (LMAX*COUT) + o];
        }
        __syncthreads();
#pragma unroll
        for (int k = 0; k < 16; k++) {
            float4 a0 = *(const float4*)&As[k][ty*8];
            float4 a1 = *(const float4*)&As[k][ty*8 + 4];
            float4 b0 = *(const float4*)&Bs[k][tx*8];
            float4 b1 = *(const float4*)&Bs[k][tx*8 + 4];
            float av[8] = {a0.x,a0.y,a0.z,a0.w,a1.x,a1.y,a1.z,a1.w};
            float bv[8] = {b0.x,b0.y,b0.z,b0.w,b1.x,b1.y,b1.z,b1.w};
#pragma unroll
            for (int i2 = 0; i2 < 8; i2++)
#pragma unroll
                for (int j2 = 0; j2 < 8; j2++)
                    acc[i2][j2] += av[i2] * bv[j2];
        }
        __syncthreads();
    }
#pragma unroll
    for (int i2 = 0; i2 < 8; i2++) {
        *(float4*)&C[(ty*8 + i2)*COUT + tx*8]     =
            make_float4(acc[i2][0], acc[i2][1], acc[i2][2], acc[i2][3]);
        *(float4*)&C[(ty*8 + i2)*COUT + tx*8 + 4] =
            make_float4(acc[i2][4], acc[i2][5], acc[i2][6], acc[i2][7]);
    }
}

// ---------------- D: Legendre synthesis ------------------------------------
__global__ void __launch_bounds__(128) kD() {
    int r = blockIdx.x;                   // (b*16+m)*2+ri
    int ri = r & 1, m = (r >> 1) & 15, b = r >> 5;
    int o = threadIdx.x;
    __shared__ float sq[LMAX*NG];         // Qs[l][m][*] (includes k_m)
    for (int t = o; t < LMAX*NG; t += 128) {
        int l = t >> 5, j = t & 31;
        sq[t] = g_Qs[(l*LMAX + m)*NG + j];
    }
    __syncthreads();

    float ch[LMAX];
#pragma unroll
    for (int l = 0; l < LMAX; l++) ch[l] = g_chat[((size_t)l*NR + r)*COUT + o];

#pragma unroll
    for (int j = 0; j < NG; j++) {
        float g = 0.f;
#pragma unroll
        for (int l = 0; l < LMAX; l++) g += sq[l*NG + j] * ch[l];
        g_G[(((((size_t)b*NG + j)*LMAX + m)*2 + ri))*COUT + o] = g;
    }
}

// ---------------- E: inverse real DFT over phi + bias ----------------------
__global__ void __launch_bounds__(128) kE(const float* __restrict__ bias, float* __restrict__ out) {
    int bj = blockIdx.x;
    int o = threadIdx.x;
    __shared__ float sc[LMAX*NG], ss[LMAX*NG];
    for (int t = o; t < LMAX*NG; t += 128) { sc[t] = g_cosT[t]; ss[t] = g_sinT[t]; }
    __syncthreads();

    float gr[LMAX], gi[LMAX];
    const float* src = g_G + (size_t)bj * LMAX * 2 * COUT + o;
#pragma unroll
    for (int m = 0; m < LMAX; m++) {
        gr[m] = src[(m*2 + 0)*COUT];
        gi[m] = src[(m*2 + 1)*COUT];
    }
    float bv = bias[o];
    float* dst = out + (size_t)bj * NG * COUT + o;
#pragma unroll
    for (int p = 0; p < NG; p++) {
        float s = bv;
#pragma unroll
        for (int m = 0; m < LMAX; m++)
            s += gr[m]*sc[m*NG + p] - gi[m]*ss[m*NG + p];
        dst[p*COUT] = s;
    }
}

extern "C" void kernel_launch(void* const* d_in, const int* in_sizes, int n_in,
                              void* d_out, int out_size) {
    const float* in   = (const float*)d_in[0];
    const float* w    = (const float*)d_in[1];
    const float* bias = (const float*)d_in[2];
    float* out = (float*)d_out;

    init_tables<<<1, 512>>>();
    kA<<<BATCH*NG, 128>>>(in);
    kB<<<NR, 128>>>();
    kC<<<dim3(16, LMAX), 256>>>(w);
    kD<<<NR, 128>>>();
    kE<<<BATCH*NG, 128>>>(bias, out);
}

// round 5
// speedup vs baseline: 6.0915x; 1.3460x over previous
#include <cuda_runtime.h>
#include <math.h>

#define BATCH 64
#define NG    32
#define CIN   128
#define COUT  128
#define LMAX  16
#define NR    (BATCH*LMAX*2)   // 2048 rows (b,m,ri) for stage C

// ---------------- scratch (device globals; no allocation allowed) ----------
__device__ float g_F[(size_t)BATCH*LMAX*2*NG*CIN];     // [b][m][ri][j][i]
__device__ float g_coef[(size_t)LMAX*NR*CIN];          // [l][r][i]
__device__ float g_chat[(size_t)LMAX*NR*COUT];         // [l][r][o]
__device__ float g_G[(size_t)BATCH*NG*LMAX*2*COUT];    // [b][j][m][ri][o]
__device__ float g_Qw[LMAX*LMAX*NG];                   // [l][m][j] * wj * s_l
__device__ float g_Qs[LMAX*LMAX*NG];                   // [l][m][j] * k_m
__device__ float g_cosT[LMAX*NG];                      // [m][p]
__device__ float g_sinT[LMAX*NG];

// ---------------- init: Legendre + trig tables, fp32, 512-way parallel -----
__global__ void init_tables() {
    int t = threadIdx.x;                  // 0..511
    int m = t >> 5, j = t & 31;           // one thread per (m, j)
    float sx, cx;
    sincospif((j + 0.5f) / NG, &sx, &cx);
    float wj = sx * ((float)M_PI / NG) * (2.0f * (float)M_PI / NG);

    for (int l = 0; l < m; l++) {
        g_Qw[(l*LMAX + m)*NG + j] = 0.f;
        g_Qs[(l*LMAX + m)*NG + j] = 0.f;
    }

    float Pmm = 1.0f, invf = 1.0f;
    for (int mm = 1; mm <= m; mm++) Pmm = -(2.0f*mm - 1.0f) * sx * Pmm;
    for (int tt = 1; tt <= 2*m; tt++) invf /= (float)tt;
    float rat = invf;
    float pl_2 = 0.0f, pl_1 = 0.0f, pl = 0.0f;
    const float inv4pi = 1.0f / (4.0f * (float)M_PI);
    for (int l = m; l < LMAX; l++) {
        if (l == m)        pl = Pmm;
        else if (l == m+1) pl = (2.0f*m + 1.0f) * cx * Pmm;
        else               pl = ((2.0f*l - 1.0f)*cx*pl_1 - (l + m - 1.0f)*pl_2) / (float)(l - m);
        float Nlm = sqrtf((2.0f*l + 1.0f) * inv4pi * rat);
        float q   = Nlm * pl;
        float sl  = 2.0f*(float)M_PI * sqrtf(4.0f*(float)M_PI / (2.0f*l + 1.0f));
        float km  = (m == 0) ? 1.0f : 2.0f;
        g_Qw[(l*LMAX + m)*NG + j] = q * wj * sl;
        g_Qs[(l*LMAX + m)*NG + j] = q * km;
        pl_2 = pl_1; pl_1 = pl;
        rat *= (float)(l + 1 - m) / (float)(l + 1 + m);
    }

    float sa, ca;
    sincospif(2.0f * (float)m * (float)j / (float)NG, &sa, &ca);
    g_cosT[m*NG + j] = ca;
    g_sinT[m*NG + j] = sa;
}

// ---------------- A: real DFT over phi (half-split), float2 channels -------
__global__ void __launch_bounds__(64) kA(const float* __restrict__ in) {
    int bj = blockIdx.x;                  // b*32 + j (theta)
    int b = bj >> 5, j = bj & 31;
    int t = threadIdx.x;                  // channel pair 0..63
    __shared__ float sc[16][16], ss[16][16];
    for (int q = t; q < 256; q += 64) {
        int m = q >> 4, p = q & 15;
        sc[m][p] = g_cosT[m*NG + p];
        ss[m][p] = g_sinT[m*NG + p];
    }
    __syncthreads();

    const float2* src = (const float2*)in + (size_t)bj * NG * 64 + t;
    float2 xe[16], xo[16];
#pragma unroll
    for (int p = 0; p < 16; p++) {
        float2 a = src[p*64], c = src[(p+16)*64];
        xe[p] = make_float2(a.x + c.x, a.y + c.y);
        xo[p] = make_float2(a.x - c.x, a.y - c.y);
    }

    float2* Fout = (float2*)g_F;
#pragma unroll
    for (int m = 0; m < 16; m++) {
        float2 fr = make_float2(0.f, 0.f), fi = make_float2(0.f, 0.f);
#pragma unroll
        for (int p = 0; p < 16; p++) {
            float c = sc[m][p], s = ss[m][p];
            float2 x = (m & 1) ? xo[p] : xe[p];   // m is compile-time
            fr.x += x.x*c; fr.y += x.y*c;
            fi.x -= x.x*s; fi.y -= x.y*s;
        }
        size_t base = ((((size_t)b*16 + m)*2 + 0)*NG + j)*64 + t;
        Fout[base]          = fr;
        Fout[base + NG*64]  = fi;   // ri=1
    }
}

// ---------------- B: Legendre analysis with reflection symmetry ------------
__global__ void __launch_bounds__(64) kB() {
    int r = blockIdx.x;                   // (b*16+m)*2+ri
    int m = (r >> 1) & 15;
    int t = threadIdx.x;
    __shared__ float sq[16][16];          // Qw[l][m][j], j<16
    for (int q = t; q < 256; q += 64) {
        int l = q >> 4, j = q & 15;
        sq[l][j] = g_Qw[(l*LMAX + m)*NG + j];
    }
    __syncthreads();

    const float2* src = (const float2*)g_F + (size_t)r * NG * 64 + t;
    float2 fe[16], fo[16];
#pragma unroll
    for (int j = 0; j < 16; j++) {
        float2 a = src[j*64], c = src[(31-j)*64];
        fe[j] = make_float2(a.x + c.x, a.y + c.y);
        fo[j] = make_float2(a.x - c.x, a.y - c.y);
    }

    float2* Cout = (float2*)g_coef;
    if ((m & 1) == 0) {
#pragma unroll
        for (int l = 0; l < 16; l++) {
            float2 acc = make_float2(0.f, 0.f);
#pragma unroll
            for (int j = 0; j < 16; j++) {
                float q = sq[l][j];
                float2 f = (l & 1) ? fo[j] : fe[j];
                acc.x += q*f.x; acc.y += q*f.y;
            }
            Cout[((size_t)l*NR + r)*64 + t] = acc;
        }
    } else {
#pragma unroll
        for (int l = 0; l < 16; l++) {
            float2 acc = make_float2(0.f, 0.f);
#pragma unroll
            for (int j = 0; j < 16; j++) {
                float q = sq[l][j];
                float2 f = (l & 1) ? fe[j] : fo[j];
                acc.x += q*f.x; acc.y += q*f.y;
            }
            Cout[((size_t)l*NR + r)*64 + t] = acc;
        }
    }
}

// ---------------- C: per-degree channel mix, 16x GEMM 2048x128x128 ---------
__global__ void __launch_bounds__(256, 2) kC(const float* __restrict__ w) {
    int l = blockIdx.y, mt = blockIdx.x;  // 16 x 16
    const float* A = g_coef + ((size_t)l*NR + (size_t)mt*128)*CIN;
    const float* B = w + l*COUT;          // w[i][l][o], k-stride = LMAX*COUT
    float* C = g_chat + ((size_t)l*NR + (size_t)mt*128)*COUT;

    __shared__ float As[16][132];
    __shared__ float Bs[16][128];
    int tid = threadIdx.x;
    int tx = tid & 15, ty = tid >> 4;
    float acc[8][8] = {};

    for (int k0 = 0; k0 < CIN; k0 += 16) {
#pragma unroll
        for (int e = 0; e < 8; e++) {
            int lin = tid + e*256;
            int r = lin >> 4, k = lin & 15;
            As[k][r] = A[r*CIN + k0 + k];
            int kk = lin >> 7, o = lin & 127;
            Bs[kk][o] = B[(size_t)(k0 + kk) * (LMAX*COUT) + o];
        }
        __syncthreads();
#pragma unroll
        for (int k = 0; k < 16; k++) {
            float4 a0 = *(const float4*)&As[k][ty*8];
            float4 a1 = *(const float4*)&As[k][ty*8 + 4];
            float4 b0 = *(const float4*)&Bs[k][tx*8];
            float4 b1 = *(const float4*)&Bs[k][tx*8 + 4];
            float av[8] = {a0.x,a0.y,a0.z,a0.w,a1.x,a1.y,a1.z,a1.w};
            float bv[8] = {b0.x,b0.y,b0.z,b0.w,b1.x,b1.y,b1.z,b1.w};
#pragma unroll
            for (int i2 = 0; i2 < 8; i2++)
#pragma unroll
                for (int j2 = 0; j2 < 8; j2++)
                    acc[i2][j2] += av[i2] * bv[j2];
        }
        __syncthreads();
    }
#pragma unroll
    for (int i2 = 0; i2 < 8; i2++) {
        *(float4*)&C[(ty*8 + i2)*COUT + tx*8]     =
            make_float4(acc[i2][0], acc[i2][1], acc[i2][2], acc[i2][3]);
        *(float4*)&C[(ty*8 + i2)*COUT + tx*8 + 4] =
            make_float4(acc[i2][4], acc[i2][5], acc[i2][6], acc[i2][7]);
    }
}

// ---------------- D: Legendre synthesis with reflection symmetry -----------
__global__ void __launch_bounds__(64) kD() {
    int r = blockIdx.x;                   // (b*16+m)*2+ri
    int ri = r & 1, m = (r >> 1) & 15, b = r >> 5;
    int t = threadIdx.x;
    __shared__ float sq[16][16];          // Qs[l][m][j], j<16 (incl. k_m)
    for (int q = t; q < 256; q += 64) {
        int l = q >> 4, j = q & 15;
        sq[l][j] = g_Qs[(l*LMAX + m)*NG + j];
    }
    __syncthreads();

    float2 ch[16];
    const float2* src = (const float2*)g_chat + (size_t)r*64 + t;
#pragma unroll
    for (int l = 0; l < 16; l++) ch[l] = src[(size_t)l*NR*64];

    float2* Gout = (float2*)g_G;
    // index for (b,j,m,ri,o2=t): (((b*32+j)*16+m)*2+ri)*64+t
    size_t gbase = ((((size_t)b*NG)*16 + m)*2 + ri)*64 + t;
    const size_t jstride = (size_t)16*2*64;

    if ((m & 1) == 0) {
#pragma unroll
        for (int j = 0; j < 16; j++) {
            float2 Ge = make_float2(0.f,0.f), Go = make_float2(0.f,0.f);
#pragma unroll
            for (int l = 0; l < 16; l++) {
                float q = sq[l][j];
                if (l & 1) { Go.x += q*ch[l].x; Go.y += q*ch[l].y; }
                else       { Ge.x += q*ch[l].x; Ge.y += q*ch[l].y; }
            }
            Gout[gbase + (size_t)j*jstride]      = make_float2(Ge.x+Go.x, Ge.y+Go.y);
            Gout[gbase + (size_t)(31-j)*jstride] = make_float2(Ge.x-Go.x, Ge.y-Go.y);
        }
    } else {
#pragma unroll
        for (int j = 0; j < 16; j++) {
            float2 Ge = make_float2(0.f,0.f), Go = make_float2(0.f,0.f);
#pragma unroll
            for (int l = 0; l < 16; l++) {
                float q = sq[l][j];
                if (l & 1) { Ge.x += q*ch[l].x; Ge.y += q*ch[l].y; }
                else       { Go.x += q*ch[l].x; Go.y += q*ch[l].y; }
            }
            Gout[gbase + (size_t)j*jstride]      = make_float2(Ge.x+Go.x, Ge.y+Go.y);
            Gout[gbase + (size_t)(31-j)*jstride] = make_float2(Ge.x-Go.x, Ge.y-Go.y);
        }
    }
}

// ---------------- E: inverse real DFT over phi (half-split) + bias ---------
__global__ void __launch_bounds__(64) kE(const float* __restrict__ bias,
                                         float* __restrict__ out) {
    int bj = blockIdx.x;                  // b*32 + j (theta)
    int t = threadIdx.x;                  // channel pair
    __shared__ float sc[16][16], ss[16][16];
    for (int q = t; q < 256; q += 64) {
        int m = q >> 4, p = q & 15;
        sc[m][p] = g_cosT[m*NG + p];
        ss[m][p] = g_sinT[m*NG + p];
    }
    __syncthreads();

    float2 gr[16], gi[16];
    const float2* src = (const float2*)g_G + (size_t)bj * 16 * 2 * 64 + t;
#pragma unroll
    for (int m = 0; m < 16; m++) {
        gr[m] = src[(m*2 + 0)*64];
        gi[m] = src[(m*2 + 1)*64];
    }
    float2 bv = ((const float2*)bias)[t];
    float2* dst = (float2*)out + (size_t)bj * NG * 64 + t;
#pragma unroll
    for (int p = 0; p < 16; p++) {
        float2 E = make_float2(0.f,0.f), O = make_float2(0.f,0.f);
#pragma unroll
        for (int m = 0; m < 16; m++) {
            float c = sc[m][p], s = ss[m][p];
            if (m & 1) {
                O.x += gr[m].x*c - gi[m].x*s;
                O.y += gr[m].y*c - gi[m].y*s;
            } else {
                E.x += gr[m].x*c - gi[m].x*s;
                E.y += gr[m].y*c - gi[m].y*s;
            }
        }
        dst[p*64]      = make_float2(bv.x + E.x + O.x, bv.y + E.y + O.y);
        dst[(p+16)*64] = make_float2(bv.x + E.x - O.x, bv.y + E.y - O.y);
    }
}

extern "C" void kernel_launch(void* const* d_in, const int* in_sizes, int n_in,
                              void* d_out, int out_size) {
    const float* in   = (const float*)d_in[0];
    const float* w    = (const float*)d_in[1];
    const float* bias = (const float*)d_in[2];
    float* out = (float*)d_out;

    init_tables<<<1, 512>>>();
    kA<<<BATCH*NG, 64>>>(in);
    kB<<<NR, 64>>>();
    kC<<<dim3(16, LMAX), 256>>>(w);
    kD<<<NR, 64>>>();
    kE<<<BATCH*NG, 64>>>(bias, out);
}